// round 13
// baseline (speedup 1.0000x reference)
#include <cuda_runtime.h>
#include <cstdint>

constexpr int TTOK=1024, HDIM=2048, EXP=32, IDIM=1024, TOPK=6, NGRP=8, TOPKG=4;
constexpr int GSIZE=EXP/NGRP, PAIRS=TTOK*TOPK;
constexpr float RSCALE=2.5f, CORR=1.0007045f;

__device__ int   g_topk_id[PAIRS];
__device__ float g_topk_w[PAIRS];
__device__ int   g_counts[EXP];
__device__ int   g_offsets[EXP];
__device__ int   g_sorted_token[PAIRS];
__device__ float g_sorted_ws[PAIRS];              // topk_w * 2.5
__device__ float g_gu   [(size_t)PAIRS*2*IDIM];   // 48MB
__device__ float g_act  [(size_t)PAIRS*IDIM];     // 24MB
__device__ float g_gu_s [(size_t)TTOK*2*IDIM];    // 8MB
__device__ float g_act_s[(size_t)TTOK*IDIM];      // 4MB

// ------------------------------ router -------------------------------------
__global__ void router_kernel(const float* __restrict__ hidden,
                              const float* __restrict__ gate_w,
                              const float* __restrict__ e_bias)
{
    int t=blockIdx.x, lane=threadIdx.x;
    const float* x=hidden+(size_t)t*HDIM;
    float logit=0.f;
    #pragma unroll 8
    for(int h=0;h<HDIM;++h) logit+=x[h]*gate_w[(size_t)h*EXP+lane];
    float s=1.f/(1.f+expf(-logit)), sc=s+e_bias[lane];
    __shared__ float sm_s[EXP], sm_sc[EXP];
    sm_s[lane]=s; sm_sc[lane]=sc; __syncwarp();
    if(lane==0){
        float gs[NGRP];
        #pragma unroll
        for(int g=0;g<NGRP;++g){
            float m1=-1e30f,m2=-1e30f;
            #pragma unroll
            for(int j=0;j<GSIZE;++j){
                float v=sm_sc[g*GSIZE+j];
                if(v>m1){m2=m1;m1=v;} else if(v>m2){m2=v;}
            }
            gs[g]=m1+m2;
        }
        bool gsel[NGRP];
        #pragma unroll
        for(int g=0;g<NGRP;++g) gsel[g]=false;
        for(int it=0;it<TOPKG;++it){
            int best=-1; float bv=-1e30f;
            for(int g=0;g<NGRP;++g) if(!gsel[g]&&gs[g]>bv){bv=gs[g];best=g;}
            gsel[best]=true;
        }
        bool taken[EXP];
        #pragma unroll
        for(int e=0;e<EXP;++e) taken[e]=false;
        int ids[TOPK]; float ws[TOPK]; float wsum=0.f;
        for(int it=0;it<TOPK;++it){
            int best=-1; float bv=-1e30f;
            for(int e=0;e<EXP;++e){
                if(!gsel[e>>2]||taken[e]) continue;
                if(sm_sc[e]>bv){bv=sm_sc[e];best=e;}
            }
            taken[best]=true; ids[it]=best; ws[it]=sm_s[best]; wsum+=ws[it];
        }
        float inv=1.f/wsum;
        #pragma unroll
        for(int k=0;k<TOPK;++k){
            g_topk_id[t*TOPK+k]=ids[k];
            g_topk_w [t*TOPK+k]=ws[k]*inv;
        }
    }
}

// ---------------- count+scan fused (single block) ---------------------------
__global__ void countscan_kernel()
{
    __shared__ int hist[EXP];
    int tid=threadIdx.x;
    if(tid<EXP) hist[tid]=0;
    __syncthreads();
    for(int p=tid;p<PAIRS;p+=blockDim.x) atomicAdd(&hist[g_topk_id[p]],1);
    __syncthreads();
    if(tid==0){
        int acc=0;
        for(int e=0;e<EXP;++e){ g_counts[e]=hist[e]; g_offsets[e]=acc; acc+=hist[e]; }
    }
}

__global__ void place_kernel()
{
    int e=blockIdx.x, tid=threadIdx.x;
    constexpr int CH=PAIRS/256;
    int p0=tid*CH, c=0;
    for(int i=0;i<CH;++i) c+=(g_topk_id[p0+i]==e);
    __shared__ int sc[256];
    sc[tid]=c; __syncthreads();
    for(int d=1;d<256;d<<=1){
        int v=(tid>=d)?sc[tid-d]:0; __syncthreads();
        sc[tid]+=v; __syncthreads();
    }
    int pos=g_offsets[e]+sc[tid]-c;
    for(int i=0;i<CH;++i){
        int p=p0+i;
        if(g_topk_id[p]==e){
            g_sorted_token[pos]=p/TOPK;
            g_sorted_ws[pos]=g_topk_w[p]*RSCALE;
            ++pos;
        }
    }
}

// --------------------------- tf32 GEMM core ---------------------------------
__device__ __forceinline__ void cp_async16(uint32_t dst,const void* src,int bytes)
{ asm volatile("cp.async.cg.shared.global [%0], [%1], 16, %2;\n"::"r"(dst),"l"(src),"r"(bytes)); }
__device__ __forceinline__ void cp_commit(){ asm volatile("cp.async.commit_group;\n"); }
template<int N> __device__ __forceinline__ void cp_wait()
{ asm volatile("cp.async.wait_group %0;\n"::"n"(N)); }

#define MMA_TF32(d, a, b)                                                  \
    asm volatile(                                                          \
        "mma.sync.aligned.m16n8k8.row.col.f32.tf32.tf32.f32 "              \
        "{%0,%1,%2,%3}, {%4,%5,%6,%7}, {%8,%9}, {%0,%1,%2,%3};\n"          \
        : "+f"(d[0]), "+f"(d[1]), "+f"(d[2]), "+f"(d[3])                   \
        : "r"(a[0]), "r"(a[1]), "r"(a[2]), "r"(a[3]), "r"(b[0]), "r"(b[1]))

// BM=64, BN=128, BK=16. 64 threads = 2 warps, EACH warp computes a 64x64
// tile (mf=4, nf=8 -> 32 MMAs per ks on 32 LDS: dispatch share ~63%).
// 4-stage cp.async pipeline, compile-time buffer indices, 4 CTAs/SM.
// Raw fp32 -> tf32 MMA (RZ); bias corrected by CORR in epilogue.
// A2 branch: blockIdx.z == gridDim.z-1 -> shared expert (A2/B2/C2/M2).
// outmap: epilogue atomically accumulates into C[outmap[row]].
constexpr int STAGES=4;
constexpr int BN=128;
constexpr int A_FLOATS=64*20;
constexpr int B_FLOATS=16*136;
constexpr int STAGE_FLOATS=A_FLOATS+B_FLOATS;          // 3456
constexpr int GEMM_SMEM_BYTES=STAGES*STAGE_FLOATS*4;   // 55296

__global__ __launch_bounds__(64,4)
void gemm_tf32_kernel(const float* __restrict__ A,
                      const float* __restrict__ Bb,
                      float* __restrict__ C,
                      int M,int N,int K,
                      const int* __restrict__ counts,
                      const int* __restrict__ offsets,
                      const int* __restrict__ rowmap,
                      const float* __restrict__ rowscale,
                      size_t strideB,
                      const float* __restrict__ A2,
                      const float* __restrict__ B2,
                      float* __restrict__ C2,
                      int M2,
                      const int* __restrict__ outmap)
{
    extern __shared__ float smem[];

    const int e=blockIdx.z;
    const bool isShared=(A2!=nullptr)&&(e==(int)gridDim.z-1);

    const float* Ause; const float* Buse; float* Cuse;
    int m_count, base;
    const int* rmap; const float* rscale; const int* omap;
    if(isShared){
        Ause=A2; Buse=B2; Cuse=C2; m_count=M2; base=0;
        rmap=nullptr; rscale=nullptr; omap=nullptr;
    } else {
        Ause=A; Buse=Bb+(size_t)e*strideB; Cuse=C;
        m_count=counts?counts[e]:M; base=offsets?offsets[e]:0;
        rmap=rowmap; rscale=rowscale; omap=outmap;
    }

    const int m0=blockIdx.x*64;
    if(m0>=m_count) return;
    const int n0=blockIdx.y*BN;

    const int tid=threadIdx.x;

    // A loader: thread owns row tid, all 4 k-quads (4 cp.async per stage)
    const int ar=tid;
    const bool avalid=(m0+ar)<m_count;
    const int grow_a=base+m0+ar;
    const int arow=avalid?(rmap?rmap[grow_a]:grow_a):0;
    const float* Ap=Ause+(size_t)arow*K;
    const int abytes=avalid?16:0;

    // B loader: thread owns rows rb+{0,4,8,12}, n-quads bq and bq+16
    const int rb=tid>>4;            // 0..3
    const int bq=tid&15;            // 0..15
    const float* Bp=Buse+(size_t)rb*N+n0+bq*4;

    const int wid=tid>>5, lane=tid&31;
    const int wn=wid*64;
    const int gid=lane>>2, tig=lane&3;

    float acc[4][8][4];
    #pragma unroll
    for(int i=0;i<4;++i)
        #pragma unroll
        for(int j=0;j<8;++j)
            #pragma unroll
            for(int k=0;k<4;++k) acc[i][j][k]=0.f;

    const int nk=K/16;   // 64 or 128; divisible by 4

    const uint32_t smem_base=(uint32_t)__cvta_generic_to_shared(smem);
    const uint32_t a_off0=smem_base+(ar*20)*4;
    const uint32_t b_off0=smem_base+(A_FLOATS+rb*136+bq*4)*4;
    constexpr uint32_t STAGE_BYTES=STAGE_FLOATS*4;
    constexpr uint32_t BROW=136*4;

    // NOTE: second B chunk covers columns +64 floats -> smem offset +256 BYTES
    #pragma unroll
    for(int s=0;s<STAGES-1;++s){
        const size_t ko=(size_t)s*16;
        #pragma unroll
        for(int q=0;q<4;++q)
            cp_async16(a_off0+s*STAGE_BYTES+q*16,Ap+ko+q*4,abytes);
        #pragma unroll
        for(int r=0;r<4;++r){
            cp_async16(b_off0+s*STAGE_BYTES+r*4*BROW,      Bp+ko*N+(size_t)(r*4)*N,16);
            cp_async16(b_off0+s*STAGE_BYTES+r*4*BROW+256,  Bp+ko*N+(size_t)(r*4)*N+64,16);
        }
        cp_commit();
    }

    for(int kb=0;kb<nk;kb+=STAGES){
        #pragma unroll
        for(int s=0;s<STAGES;++s){
            const int kt=kb+s;
            cp_wait<STAGES-2>();
            __syncthreads();

            const int kf=kt+STAGES-1;
            if(kf<nk){
                const int fb=(s+STAGES-1)%STAGES;
                const size_t ko=(size_t)kf*16;
                #pragma unroll
                for(int q=0;q<4;++q)
                    cp_async16(a_off0+fb*STAGE_BYTES+q*16,Ap+ko+q*4,abytes);
                #pragma unroll
                for(int r=0;r<4;++r){
                    cp_async16(b_off0+fb*STAGE_BYTES+r*4*BROW,     Bp+ko*N+(size_t)(r*4)*N,16);
                    cp_async16(b_off0+fb*STAGE_BYTES+r*4*BROW+256, Bp+ko*N+(size_t)(r*4)*N+64,16);
                }
            }
            cp_commit();

            const uint32_t* As=(const uint32_t*)(smem+s*STAGE_FLOATS);
            const uint32_t* Bs=As+A_FLOATS;

            #pragma unroll
            for(int ks=0;ks<2;++ks){
                const int kk=ks*8;
                uint32_t a[4][4], b[8][2];
                #pragma unroll
                for(int mf=0;mf<4;++mf){
                    const int mr=mf*16+gid;
                    a[mf][0]=As[(mr   )*20+kk+tig];
                    a[mf][1]=As[(mr+8)*20+kk+tig];
                    a[mf][2]=As[(mr   )*20+kk+tig+4];
                    a[mf][3]=As[(mr+8)*20+kk+tig+4];
                }
                #pragma unroll
                for(int nf=0;nf<8;++nf){
                    const int nc=wn+nf*8+gid;
                    b[nf][0]=Bs[(kk+tig   )*136+nc];
                    b[nf][1]=Bs[(kk+tig+4)*136+nc];
                }
                #pragma unroll
                for(int mf=0;mf<4;++mf)
                    #pragma unroll
                    for(int nf=0;nf<8;++nf)
                        MMA_TF32(acc[mf][nf],a[mf],b[nf]);
            }
        }
    }

    // epilogue: CORR folded into scale; atomic accumulate if omap given
    #pragma unroll
    for(int mf=0;mf<4;++mf){
        #pragma unroll
        for(int half=0;half<2;++half){
            const int rloc=mf*16+gid+half*8;
            if(m0+rloc<m_count){
                const int grow=base+m0+rloc;
                const float scl=(rscale?rscale[grow]:1.f)*CORR;
                const int orow=omap?omap[grow]:grow;
                float* crow=Cuse+(size_t)orow*N+n0+wn;
                if(omap){
                    #pragma unroll
                    for(int nf=0;nf<8;++nf){
                        atomicAdd(crow+nf*8+tig*2,   acc[mf][nf][half*2+0]*scl);
                        atomicAdd(crow+nf*8+tig*2+1, acc[mf][nf][half*2+1]*scl);
                    }
                } else {
                    #pragma unroll
                    for(int nf=0;nf<8;++nf){
                        float2 v;
                        v.x=acc[mf][nf][half*2+0]*scl;
                        v.y=acc[mf][nf][half*2+1]*scl;
                        *(float2*)(crow+nf*8+tig*2)=v;
                    }
                }
            }
        }
    }
}

// --------------------------- silu * mul -------------------------------------
__global__ void silu_mul_kernel(const float* __restrict__ gu,
                                float* __restrict__ act,int rows)
{
    const int QI=IDIM/4;
    int total=rows*QI;
    for(int idx=blockIdx.x*blockDim.x+threadIdx.x;idx<total;
        idx+=gridDim.x*blockDim.x){
        int r=idx/QI, q=idx-r*QI;
        const float* row=gu+(size_t)r*2*IDIM;
        float4 g=*(const float4*)(row+q*4);
        float4 u=*(const float4*)(row+IDIM+q*4);
        float4 o;
        o.x=g.x/(1.f+__expf(-g.x))*u.x;
        o.y=g.y/(1.f+__expf(-g.y))*u.y;
        o.z=g.z/(1.f+__expf(-g.z))*u.z;
        o.w=g.w/(1.f+__expf(-g.w))*u.w;
        *(float4*)(act+(size_t)r*IDIM+q*4)=o;
    }
}

// --------------------------- launch -----------------------------------------
extern "C" void kernel_launch(void* const* d_in,const int* in_sizes,int n_in,
                              void* d_out,int out_size)
{
    const float* hidden   =(const float*)d_in[0];
    const float* gate_w   =(const float*)d_in[1];
    const float* e_bias   =(const float*)d_in[2];
    const float* w_gate_up=(const float*)d_in[3];
    const float* w_down   =(const float*)d_in[4];
    const float* sh_gu    =(const float*)d_in[5];
    const float* sh_down  =(const float*)d_in[6];
    float* out            =(float*)d_out;

    void *p_gu,*p_act,*p_gu_s,*p_act_s,*p_counts,*p_offsets,*p_stok,*p_sws;
    cudaGetSymbolAddress(&p_gu,g_gu);
    cudaGetSymbolAddress(&p_act,g_act);
    cudaGetSymbolAddress(&p_gu_s,g_gu_s);
    cudaGetSymbolAddress(&p_act_s,g_act_s);
    cudaGetSymbolAddress(&p_counts,g_counts);
    cudaGetSymbolAddress(&p_offsets,g_offsets);
    cudaGetSymbolAddress(&p_stok,g_sorted_token);
    cudaGetSymbolAddress(&p_sws,g_sorted_ws);

    static bool attr_set=false;
    if(!attr_set){
        cudaFuncSetAttribute(gemm_tf32_kernel,
                             cudaFuncAttributeMaxDynamicSharedMemorySize,
                             GEMM_SMEM_BYTES);
        attr_set=true;
    }

    // 0-2: router + fused count/scan + place
    router_kernel<<<TTOK,32>>>(hidden,gate_w,e_bias);
    countscan_kernel<<<1,256>>>();
    place_kernel<<<EXP,256>>>();

    // 3 (ncu profiles this): MERGED gate_up GEMM — z<32 routed, z==32 shared
    gemm_tf32_kernel<<<dim3(16,2*IDIM/BN,EXP+1),64,GEMM_SMEM_BYTES>>>(
        hidden,w_gate_up,(float*)p_gu, 0,2*IDIM,HDIM,
        (const int*)p_counts,(const int*)p_offsets,(const int*)p_stok,nullptr,
        (size_t)HDIM*2*IDIM,
        hidden,sh_gu,(float*)p_gu_s,TTOK, nullptr);

    // silu*mul for routed and shared activations
    silu_mul_kernel<<<6144,256>>>((const float*)p_gu,(float*)p_act,PAIRS);
    silu_mul_kernel<<<1024,256>>>((const float*)p_gu_s,(float*)p_act_s,TTOK);

    // shared down-proj: writes out directly (initializes every element)
    gemm_tf32_kernel<<<dim3(16,HDIM/BN,1),64,GEMM_SMEM_BYTES>>>(
        (const float*)p_act_s,sh_down,out, TTOK,HDIM,IDIM,
        nullptr,nullptr,nullptr,nullptr,0,
        nullptr,nullptr,nullptr,0, nullptr);

    // routed down-proj: atomically accumulates w*2.5*y into out[token]
    gemm_tf32_kernel<<<dim3(16,HDIM/BN,EXP),64,GEMM_SMEM_BYTES>>>(
        (const float*)p_act,w_down,out, 0,HDIM,IDIM,
        (const int*)p_counts,(const int*)p_offsets,nullptr,
        (const float*)p_sws,(size_t)IDIM*HDIM,
        nullptr,nullptr,nullptr,0, (const int*)p_stok);
}

// round 14
// speedup vs baseline: 1.1605x; 1.1605x over previous
#include <cuda_runtime.h>
#include <cstdint>

constexpr int TTOK=1024, HDIM=2048, EXP=32, IDIM=1024, TOPK=6, NGRP=8, TOPKG=4;
constexpr int GSIZE=EXP/NGRP, PAIRS=TTOK*TOPK;
constexpr float RSCALE=2.5f, CORR=1.0007045f;

__device__ int   g_topk_id[PAIRS];
__device__ float g_topk_w[PAIRS];
__device__ int   g_counts[EXP];
__device__ int   g_offsets[EXP];
__device__ int   g_sorted_token[PAIRS];
__device__ float g_sorted_ws[PAIRS];              // topk_w * 2.5
__device__ float g_gu   [(size_t)PAIRS*2*IDIM];   // 48MB
__device__ float g_act  [(size_t)PAIRS*IDIM];     // 24MB
__device__ float g_gu_s [(size_t)TTOK*2*IDIM];    // 8MB
__device__ float g_act_s[(size_t)TTOK*IDIM];      // 4MB

// ------------------------------ router -------------------------------------
__global__ void router_kernel(const float* __restrict__ hidden,
                              const float* __restrict__ gate_w,
                              const float* __restrict__ e_bias)
{
    int t=blockIdx.x, lane=threadIdx.x;
    const float* x=hidden+(size_t)t*HDIM;
    float logit=0.f;
    #pragma unroll 8
    for(int h=0;h<HDIM;++h) logit+=x[h]*gate_w[(size_t)h*EXP+lane];
    float s=1.f/(1.f+expf(-logit)), sc=s+e_bias[lane];
    __shared__ float sm_s[EXP], sm_sc[EXP];
    sm_s[lane]=s; sm_sc[lane]=sc; __syncwarp();
    if(lane==0){
        float gs[NGRP];
        #pragma unroll
        for(int g=0;g<NGRP;++g){
            float m1=-1e30f,m2=-1e30f;
            #pragma unroll
            for(int j=0;j<GSIZE;++j){
                float v=sm_sc[g*GSIZE+j];
                if(v>m1){m2=m1;m1=v;} else if(v>m2){m2=v;}
            }
            gs[g]=m1+m2;
        }
        bool gsel[NGRP];
        #pragma unroll
        for(int g=0;g<NGRP;++g) gsel[g]=false;
        for(int it=0;it<TOPKG;++it){
            int best=-1; float bv=-1e30f;
            for(int g=0;g<NGRP;++g) if(!gsel[g]&&gs[g]>bv){bv=gs[g];best=g;}
            gsel[best]=true;
        }
        bool taken[EXP];
        #pragma unroll
        for(int e=0;e<EXP;++e) taken[e]=false;
        int ids[TOPK]; float ws[TOPK]; float wsum=0.f;
        for(int it=0;it<TOPK;++it){
            int best=-1; float bv=-1e30f;
            for(int e=0;e<EXP;++e){
                if(!gsel[e>>2]||taken[e]) continue;
                if(sm_sc[e]>bv){bv=sm_sc[e];best=e;}
            }
            taken[best]=true; ids[it]=best; ws[it]=sm_s[best]; wsum+=ws[it];
        }
        float inv=1.f/wsum;
        #pragma unroll
        for(int k=0;k<TOPK;++k){
            g_topk_id[t*TOPK+k]=ids[k];
            g_topk_w [t*TOPK+k]=ws[k]*inv;
        }
    }
}

// ---------------- count+scan fused (single block) ---------------------------
__global__ void countscan_kernel()
{
    __shared__ int hist[EXP];
    int tid=threadIdx.x;
    if(tid<EXP) hist[tid]=0;
    __syncthreads();
    for(int p=tid;p<PAIRS;p+=blockDim.x) atomicAdd(&hist[g_topk_id[p]],1);
    __syncthreads();
    if(tid==0){
        int acc=0;
        for(int e=0;e<EXP;++e){ g_counts[e]=hist[e]; g_offsets[e]=acc; acc+=hist[e]; }
    }
}

__global__ void place_kernel()
{
    int e=blockIdx.x, tid=threadIdx.x;
    constexpr int CH=PAIRS/256;
    int p0=tid*CH, c=0;
    for(int i=0;i<CH;++i) c+=(g_topk_id[p0+i]==e);
    __shared__ int sc[256];
    sc[tid]=c; __syncthreads();
    for(int d=1;d<256;d<<=1){
        int v=(tid>=d)?sc[tid-d]:0; __syncthreads();
        sc[tid]+=v; __syncthreads();
    }
    int pos=g_offsets[e]+sc[tid]-c;
    for(int i=0;i<CH;++i){
        int p=p0+i;
        if(g_topk_id[p]==e){
            g_sorted_token[pos]=p/TOPK;
            g_sorted_ws[pos]=g_topk_w[p]*RSCALE;
            ++pos;
        }
    }
}

// --------------------------- tf32 GEMM core ---------------------------------
__device__ __forceinline__ void cp_async16(uint32_t dst,const void* src,int bytes)
{ asm volatile("cp.async.cg.shared.global [%0], [%1], 16, %2;\n"::"r"(dst),"l"(src),"r"(bytes)); }
__device__ __forceinline__ void cp_commit(){ asm volatile("cp.async.commit_group;\n"); }
template<int N> __device__ __forceinline__ void cp_wait()
{ asm volatile("cp.async.wait_group %0;\n"::"n"(N)); }

#define MMA_TF32(d, a, b)                                                  \
    asm volatile(                                                          \
        "mma.sync.aligned.m16n8k8.row.col.f32.tf32.tf32.f32 "              \
        "{%0,%1,%2,%3}, {%4,%5,%6,%7}, {%8,%9}, {%0,%1,%2,%3};\n"          \
        : "+f"(d[0]), "+f"(d[1]), "+f"(d[2]), "+f"(d[3])                   \
        : "r"(a[0]), "r"(a[1]), "r"(a[2]), "r"(a[3]), "r"(b[0]), "r"(b[1]))

// BM=64, BN=128, BK=32. 128 threads, 4 warps (2m x 2n), warp tile 32x64
// (R11 core). 2-stage pipeline, 4 CTAs/SM. BK=32 halves per-K barrier /
// cp_wait overhead (stall amortization).
// Raw fp32 -> tf32 MMA (RZ); bias corrected by CORR in epilogue.
// A2 branch: blockIdx.z == gridDim.z-1 -> shared expert.
// outmap: epilogue atomically accumulates into C[outmap[row]].
constexpr int STAGES=2;
constexpr int BN=128;
constexpr int A_FLOATS=64*36;                      // [m][k] stride 36
constexpr int B_FLOATS=32*136;                     // [k][n] stride 136
constexpr int STAGE_FLOATS=A_FLOATS+B_FLOATS;      // 6656
constexpr int GEMM_SMEM_BYTES=STAGES*STAGE_FLOATS*4;  // 53248

__global__ __launch_bounds__(128,4)
void gemm_tf32_kernel(const float* __restrict__ A,
                      const float* __restrict__ Bb,
                      float* __restrict__ C,
                      int M,int N,int K,
                      const int* __restrict__ counts,
                      const int* __restrict__ offsets,
                      const int* __restrict__ rowmap,
                      const float* __restrict__ rowscale,
                      size_t strideB,
                      const float* __restrict__ A2,
                      const float* __restrict__ B2,
                      float* __restrict__ C2,
                      int M2,
                      const int* __restrict__ outmap)
{
    extern __shared__ float smem[];

    const int e=blockIdx.z;
    const bool isShared=(A2!=nullptr)&&(e==(int)gridDim.z-1);

    const float* Ause; const float* Buse; float* Cuse;
    int m_count, base;
    const int* rmap; const float* rscale; const int* omap;
    if(isShared){
        Ause=A2; Buse=B2; Cuse=C2; m_count=M2; base=0;
        rmap=nullptr; rscale=nullptr; omap=nullptr;
    } else {
        Ause=A; Buse=Bb+(size_t)e*strideB; Cuse=C;
        m_count=counts?counts[e]:M; base=offsets?offsets[e]:0;
        rmap=rowmap; rscale=rowscale; omap=outmap;
    }

    const int m0=blockIdx.x*64;
    if(m0>=m_count) return;
    const int n0=blockIdx.y*BN;

    const int tid=threadIdx.x;

    // A loader: thread owns row ar (2 threads/row), 4 k-quads starting at aq
    const int ar=tid>>1;                 // 0..63
    const int aq=(tid&1)*4;              // 0 or 4 (quad index, 4 quads each)
    const bool avalid=(m0+ar)<m_count;
    const int grow_a=base+m0+ar;
    const int arow=avalid?(rmap?rmap[grow_a]:grow_a):0;
    const float* Ap=Ause+(size_t)arow*K;
    const int abytes=avalid?16:0;

    // B loader: thread owns k-rows bkr+{0,4,...,28}, n-quad bnq (8 cp.async)
    const int bkr=tid>>5;                // 0..3
    const int bnq=tid&31;                // 0..31
    const float* Bp=Buse+(size_t)bkr*N+n0+bnq*4;

    const int wid=tid>>5, lane=tid&31;
    const int wm=(wid>>1)*32, wn=(wid&1)*64;
    const int gid=lane>>2, tig=lane&3;

    float acc[2][8][4];
    #pragma unroll
    for(int i=0;i<2;++i)
        #pragma unroll
        for(int j=0;j<8;++j)
            #pragma unroll
            for(int k=0;k<4;++k) acc[i][j][k]=0.f;

    const int nk=K/32;   // 64 or 32

    const uint32_t smem_base=(uint32_t)__cvta_generic_to_shared(smem);
    const uint32_t a_off0=smem_base+(ar*36+aq*4)*4;
    const uint32_t b_off0=smem_base+(A_FLOATS+bkr*136+bnq*4)*4;
    constexpr uint32_t STAGE_BYTES=STAGE_FLOATS*4;
    constexpr uint32_t BROW=136*4;

    // stage tile j into buffer fb
    auto stage=[&](int j,int fb){
        const size_t ko=(size_t)j*32;
        const uint32_t ab=a_off0+fb*STAGE_BYTES;
        #pragma unroll
        for(int q=0;q<4;++q)
            cp_async16(ab+q*16,Ap+ko+(aq+q)*4,abytes);
        const uint32_t bb=b_off0+fb*STAGE_BYTES;
        #pragma unroll
        for(int r=0;r<8;++r)
            cp_async16(bb+r*4*BROW,Bp+ko*N+(size_t)(r*4)*N,16);
    };

    // prologue: tile 0 -> buffer 0
    stage(0,0);
    cp_commit();

    for(int kt=0;kt<nk;++kt){
        cp_wait<0>();          // tile kt fully arrived (all threads' groups)
        __syncthreads();       // visibility + frees buffer (kt+1)&1

        if(kt+1<nk) stage(kt+1,(kt+1)&1);
        cp_commit();

        const uint32_t* As=(const uint32_t*)(smem+(kt&1)*STAGE_FLOATS);
        const uint32_t* Bs=As+A_FLOATS;

        #pragma unroll
        for(int ks=0;ks<4;++ks){
            const int kk=ks*8;
            uint32_t a[2][4], b[8][2];
            #pragma unroll
            for(int mf=0;mf<2;++mf){
                const int mr=wm+mf*16+gid;
                a[mf][0]=As[(mr   )*36+kk+tig];
                a[mf][1]=As[(mr+8)*36+kk+tig];
                a[mf][2]=As[(mr   )*36+kk+tig+4];
                a[mf][3]=As[(mr+8)*36+kk+tig+4];
            }
            #pragma unroll
            for(int nf=0;nf<8;++nf){
                const int nc=wn+nf*8+gid;
                b[nf][0]=Bs[(kk+tig   )*136+nc];
                b[nf][1]=Bs[(kk+tig+4)*136+nc];
            }
            #pragma unroll
            for(int mf=0;mf<2;++mf)
                #pragma unroll
                for(int nf=0;nf<8;++nf)
                    MMA_TF32(acc[mf][nf],a[mf],b[nf]);
        }
    }

    // epilogue: CORR folded into scale; atomic accumulate if omap given
    #pragma unroll
    for(int mf=0;mf<2;++mf){
        #pragma unroll
        for(int half=0;half<2;++half){
            const int rloc=wm+mf*16+gid+half*8;
            if(m0+rloc<m_count){
                const int grow=base+m0+rloc;
                const float scl=(rscale?rscale[grow]:1.f)*CORR;
                const int orow=omap?omap[grow]:grow;
                float* crow=Cuse+(size_t)orow*N+n0+wn;
                if(omap){
                    #pragma unroll
                    for(int nf=0;nf<8;++nf){
                        atomicAdd(crow+nf*8+tig*2,   acc[mf][nf][half*2+0]*scl);
                        atomicAdd(crow+nf*8+tig*2+1, acc[mf][nf][half*2+1]*scl);
                    }
                } else {
                    #pragma unroll
                    for(int nf=0;nf<8;++nf){
                        float2 v;
                        v.x=acc[mf][nf][half*2+0]*scl;
                        v.y=acc[mf][nf][half*2+1]*scl;
                        *(float2*)(crow+nf*8+tig*2)=v;
                    }
                }
            }
        }
    }
}

// --------------------------- silu * mul -------------------------------------
__global__ void silu_mul_kernel(const float* __restrict__ gu,
                                float* __restrict__ act,int rows)
{
    const int QI=IDIM/4;
    int total=rows*QI;
    for(int idx=blockIdx.x*blockDim.x+threadIdx.x;idx<total;
        idx+=gridDim.x*blockDim.x){
        int r=idx/QI, q=idx-r*QI;
        const float* row=gu+(size_t)r*2*IDIM;
        float4 g=*(const float4*)(row+q*4);
        float4 u=*(const float4*)(row+IDIM+q*4);
        float4 o;
        o.x=g.x/(1.f+__expf(-g.x))*u.x;
        o.y=g.y/(1.f+__expf(-g.y))*u.y;
        o.z=g.z/(1.f+__expf(-g.z))*u.z;
        o.w=g.w/(1.f+__expf(-g.w))*u.w;
        *(float4*)(act+(size_t)r*IDIM+q*4)=o;
    }
}

// --------------------------- launch -----------------------------------------
extern "C" void kernel_launch(void* const* d_in,const int* in_sizes,int n_in,
                              void* d_out,int out_size)
{
    const float* hidden   =(const float*)d_in[0];
    const float* gate_w   =(const float*)d_in[1];
    const float* e_bias   =(const float*)d_in[2];
    const float* w_gate_up=(const float*)d_in[3];
    const float* w_down   =(const float*)d_in[4];
    const float* sh_gu    =(const float*)d_in[5];
    const float* sh_down  =(const float*)d_in[6];
    float* out            =(float*)d_out;

    void *p_gu,*p_act,*p_gu_s,*p_act_s,*p_counts,*p_offsets,*p_stok,*p_sws;
    cudaGetSymbolAddress(&p_gu,g_gu);
    cudaGetSymbolAddress(&p_act,g_act);
    cudaGetSymbolAddress(&p_gu_s,g_gu_s);
    cudaGetSymbolAddress(&p_act_s,g_act_s);
    cudaGetSymbolAddress(&p_counts,g_counts);
    cudaGetSymbolAddress(&p_offsets,g_offsets);
    cudaGetSymbolAddress(&p_stok,g_sorted_token);
    cudaGetSymbolAddress(&p_sws,g_sorted_ws);

    static bool attr_set=false;
    if(!attr_set){
        cudaFuncSetAttribute(gemm_tf32_kernel,
                             cudaFuncAttributeMaxDynamicSharedMemorySize,
                             GEMM_SMEM_BYTES);
        attr_set=true;
    }

    // 0-2: router + fused count/scan + place
    router_kernel<<<TTOK,32>>>(hidden,gate_w,e_bias);
    countscan_kernel<<<1,256>>>();
    place_kernel<<<EXP,256>>>();

    // 3 (ncu profiles this): MERGED gate_up GEMM — z<32 routed, z==32 shared
    gemm_tf32_kernel<<<dim3(16,2*IDIM/BN,EXP+1),128,GEMM_SMEM_BYTES>>>(
        hidden,w_gate_up,(float*)p_gu, 0,2*IDIM,HDIM,
        (const int*)p_counts,(const int*)p_offsets,(const int*)p_stok,nullptr,
        (size_t)HDIM*2*IDIM,
        hidden,sh_gu,(float*)p_gu_s,TTOK, nullptr);

    // silu*mul for routed and shared activations
    silu_mul_kernel<<<6144,256>>>((const float*)p_gu,(float*)p_act,PAIRS);
    silu_mul_kernel<<<1024,256>>>((const float*)p_gu_s,(float*)p_act_s,TTOK);

    // shared down-proj: writes out directly (initializes every element)
    gemm_tf32_kernel<<<dim3(16,HDIM/BN,1),128,GEMM_SMEM_BYTES>>>(
        (const float*)p_act_s,sh_down,out, TTOK,HDIM,IDIM,
        nullptr,nullptr,nullptr,nullptr,0,
        nullptr,nullptr,nullptr,0, nullptr);

    // routed down-proj: atomically accumulates w*2.5*y into out[token]
    gemm_tf32_kernel<<<dim3(16,HDIM/BN,EXP),128,GEMM_SMEM_BYTES>>>(
        (const float*)p_act,w_down,out, 0,HDIM,IDIM,
        (const int*)p_counts,(const int*)p_offsets,nullptr,
        (const float*)p_sws,(size_t)IDIM*HDIM,
        nullptr,nullptr,nullptr,0, (const int*)p_stok);
}

// round 15
// speedup vs baseline: 1.2983x; 1.1187x over previous
#include <cuda_runtime.h>
#include <cstdint>

constexpr int TTOK=1024, HDIM=2048, EXP=32, IDIM=1024, TOPK=6, NGRP=8, TOPKG=4;
constexpr int GSIZE=EXP/NGRP, PAIRS=TTOK*TOPK;
constexpr float RSCALE=2.5f, CORR=1.0007045f;

__device__ int   g_topk_id[PAIRS];
__device__ float g_topk_w[PAIRS];
__device__ int   g_counts[EXP];
__device__ int   g_offsets[EXP];
__device__ int   g_sorted_token[PAIRS];
__device__ float g_sorted_ws[PAIRS];              // topk_w * 2.5
__device__ float g_act  [(size_t)PAIRS*IDIM];     // 24MB (silu(g)*u, routed)
__device__ float g_act_s[(size_t)TTOK*IDIM];      // 4MB  (silu(g)*u, shared)

// ------------------------------ router -------------------------------------
__global__ void router_kernel(const float* __restrict__ hidden,
                              const float* __restrict__ gate_w,
                              const float* __restrict__ e_bias)
{
    int t=blockIdx.x, lane=threadIdx.x;
    const float* x=hidden+(size_t)t*HDIM;
    float logit=0.f;
    #pragma unroll 8
    for(int h=0;h<HDIM;++h) logit+=x[h]*gate_w[(size_t)h*EXP+lane];
    float s=1.f/(1.f+expf(-logit)), sc=s+e_bias[lane];
    __shared__ float sm_s[EXP], sm_sc[EXP];
    sm_s[lane]=s; sm_sc[lane]=sc; __syncwarp();
    if(lane==0){
        float gs[NGRP];
        #pragma unroll
        for(int g=0;g<NGRP;++g){
            float m1=-1e30f,m2=-1e30f;
            #pragma unroll
            for(int j=0;j<GSIZE;++j){
                float v=sm_sc[g*GSIZE+j];
                if(v>m1){m2=m1;m1=v;} else if(v>m2){m2=v;}
            }
            gs[g]=m1+m2;
        }
        bool gsel[NGRP];
        #pragma unroll
        for(int g=0;g<NGRP;++g) gsel[g]=false;
        for(int it=0;it<TOPKG;++it){
            int best=-1; float bv=-1e30f;
            for(int g=0;g<NGRP;++g) if(!gsel[g]&&gs[g]>bv){bv=gs[g];best=g;}
            gsel[best]=true;
        }
        bool taken[EXP];
        #pragma unroll
        for(int e=0;e<EXP;++e) taken[e]=false;
        int ids[TOPK]; float ws[TOPK]; float wsum=0.f;
        for(int it=0;it<TOPK;++it){
            int best=-1; float bv=-1e30f;
            for(int e=0;e<EXP;++e){
                if(!gsel[e>>2]||taken[e]) continue;
                if(sm_sc[e]>bv){bv=sm_sc[e];best=e;}
            }
            taken[best]=true; ids[it]=best; ws[it]=sm_s[best]; wsum+=ws[it];
        }
        float inv=1.f/wsum;
        #pragma unroll
        for(int k=0;k<TOPK;++k){
            g_topk_id[t*TOPK+k]=ids[k];
            g_topk_w [t*TOPK+k]=ws[k]*inv;
        }
    }
}

// ---------------- count+scan fused (single block) ---------------------------
__global__ void countscan_kernel()
{
    __shared__ int hist[EXP];
    int tid=threadIdx.x;
    if(tid<EXP) hist[tid]=0;
    __syncthreads();
    for(int p=tid;p<PAIRS;p+=blockDim.x) atomicAdd(&hist[g_topk_id[p]],1);
    __syncthreads();
    if(tid==0){
        int acc=0;
        for(int e=0;e<EXP;++e){ g_counts[e]=hist[e]; g_offsets[e]=acc; acc+=hist[e]; }
    }
}

__global__ void place_kernel()
{
    int e=blockIdx.x, tid=threadIdx.x;
    constexpr int CH=PAIRS/256;
    int p0=tid*CH, c=0;
    for(int i=0;i<CH;++i) c+=(g_topk_id[p0+i]==e);
    __shared__ int sc[256];
    sc[tid]=c; __syncthreads();
    for(int d=1;d<256;d<<=1){
        int v=(tid>=d)?sc[tid-d]:0; __syncthreads();
        sc[tid]+=v; __syncthreads();
    }
    int pos=g_offsets[e]+sc[tid]-c;
    for(int i=0;i<CH;++i){
        int p=p0+i;
        if(g_topk_id[p]==e){
            g_sorted_token[pos]=p/TOPK;
            g_sorted_ws[pos]=g_topk_w[p]*RSCALE;
            ++pos;
        }
    }
}

// --------------------------- tf32 GEMM core ---------------------------------
__device__ __forceinline__ void cp_async16(uint32_t dst,const void* src,int bytes)
{ asm volatile("cp.async.cg.shared.global [%0], [%1], 16, %2;\n"::"r"(dst),"l"(src),"r"(bytes)); }
__device__ __forceinline__ void cp_commit(){ asm volatile("cp.async.commit_group;\n"); }
template<int N> __device__ __forceinline__ void cp_wait()
{ asm volatile("cp.async.wait_group %0;\n"::"n"(N)); }

#define MMA_TF32(d, a, b)                                                  \
    asm volatile(                                                          \
        "mma.sync.aligned.m16n8k8.row.col.f32.tf32.tf32.f32 "              \
        "{%0,%1,%2,%3}, {%4,%5,%6,%7}, {%8,%9}, {%0,%1,%2,%3};\n"          \
        : "+f"(d[0]), "+f"(d[1]), "+f"(d[2]), "+f"(d[3])                   \
        : "r"(a[0]), "r"(a[1]), "r"(a[2]), "r"(a[3]), "r"(b[0]), "r"(b[1]))

// BM=64, BN=128, BK=16, 128 threads, 4 warps (2m x 2n), warp tile 32x64.
// 4-stage cp.async pipeline (R11 core, best measured: tensor 52%).
// fuseSilu: B columns are drawn from BOTH halves of the [K,2I] gate_up
// weight so that fragments nf<4 hold g and nf>=4 hold u for the SAME output
// columns in the SAME thread; epilogue writes silu(g*CORR)*(u*CORR) to the
// activation buffer (stride IDIM). Removes g_gu buffers + silu kernels.
// A2 branch: blockIdx.z == gridDim.z-1 -> shared expert.
// outmap: epilogue atomically accumulates into C[outmap[row]].
constexpr int STAGES=4;
constexpr int BN=128;
constexpr int A_FLOATS=64*20;
constexpr int B_FLOATS=16*136;
constexpr int STAGE_FLOATS=A_FLOATS+B_FLOATS;          // 3456
constexpr int GEMM_SMEM_BYTES=STAGES*STAGE_FLOATS*4;   // 55296

__global__ __launch_bounds__(128,4)
void gemm_tf32_kernel(const float* __restrict__ A,
                      const float* __restrict__ Bb,
                      float* __restrict__ C,
                      int M,int N,int K,
                      const int* __restrict__ counts,
                      const int* __restrict__ offsets,
                      const int* __restrict__ rowmap,
                      const float* __restrict__ rowscale,
                      size_t strideB,
                      const float* __restrict__ A2,
                      const float* __restrict__ B2,
                      float* __restrict__ C2,
                      int M2,
                      const int* __restrict__ outmap,
                      int fuseSilu)
{
    extern __shared__ float smem[];

    const int e=blockIdx.z;
    const bool isShared=(A2!=nullptr)&&(e==(int)gridDim.z-1);

    const float* Ause; const float* Buse; float* Cuse;
    int m_count, base;
    const int* rmap; const float* rscale; const int* omap;
    if(isShared){
        Ause=A2; Buse=B2; Cuse=C2; m_count=M2; base=0;
        rmap=nullptr; rscale=nullptr; omap=nullptr;
    } else {
        Ause=A; Buse=Bb+(size_t)e*strideB; Cuse=C;
        m_count=counts?counts[e]:M; base=offsets?offsets[e]:0;
        rmap=rowmap; rscale=rowscale; omap=outmap;
    }

    const int m0=blockIdx.x*64;
    if(m0>=m_count) return;
    const int n0 =blockIdx.y*BN;     // plain GEMM: 128 output cols
    const int n0g=blockIdx.y*64;     // fused: 64 activation cols

    const int tid=threadIdx.x;

    // A loader: thread owns row ar, two k-quads
    const int ar=tid>>1;
    const int aq=(tid&1)*2;
    const bool avalid=(m0+ar)<m_count;
    const int grow_a=base+m0+ar;
    const int arow=avalid?(rmap?rmap[grow_a]:grow_a):0;
    const float* Ap=Ause+(size_t)arow*K+aq*4;
    const int abytes=avalid?16:0;

    // B loader: k-rows bkr+{0,4,8,12}, n-quad bnq.
    // fused: smem col block w=c0/64, cw=c0%64; cw<32 -> gate col, else up col.
    const int bkr=tid>>5;
    const int bnq=tid&31;
    const int c0=bnq*4;
    int bcol;
    if(fuseSilu){
        const int w=c0>>6, cw=c0&63;
        bcol=(cw<32)?(n0g+w*32+cw):(IDIM+n0g+w*32+(cw-32));
    } else {
        bcol=n0+c0;
    }
    const float* Bp=Buse+(size_t)bkr*N+bcol;

    const int wid=tid>>5, lane=tid&31;
    const int wm=(wid>>1)*32, wn=(wid&1)*64;
    const int wnum=wid&1;
    const int gid=lane>>2, tig=lane&3;

    float acc[2][8][4];
    #pragma unroll
    for(int i=0;i<2;++i)
        #pragma unroll
        for(int j=0;j<8;++j)
            #pragma unroll
            for(int k=0;k<4;++k) acc[i][j][k]=0.f;

    const int nk=K/16;   // 64 or 128; divisible by 4

    const uint32_t smem_base=(uint32_t)__cvta_generic_to_shared(smem);
    const uint32_t a_off0=smem_base+(ar*20+aq*4)*4;
    const uint32_t b_off0=smem_base+(A_FLOATS+bkr*136+bnq*4)*4;
    constexpr uint32_t STAGE_BYTES=STAGE_FLOATS*4;

    #pragma unroll
    for(int s=0;s<STAGES-1;++s){
        const size_t ko=(size_t)s*16;
        cp_async16(a_off0+s*STAGE_BYTES,Ap+ko,abytes);
        cp_async16(a_off0+s*STAGE_BYTES+16,Ap+ko+4,abytes);
        #pragma unroll
        for(int r=0;r<4;++r)
            cp_async16(b_off0+s*STAGE_BYTES+r*(4*136*4),
                       Bp+ko*N+(size_t)(r*4)*N,16);
        cp_commit();
    }

    for(int kb=0;kb<nk;kb+=STAGES){
        #pragma unroll
        for(int s=0;s<STAGES;++s){
            const int kt=kb+s;
            cp_wait<STAGES-2>();
            __syncthreads();

            const int kf=kt+STAGES-1;
            if(kf<nk){
                const int fb=(s+STAGES-1)%STAGES;
                const size_t ko=(size_t)kf*16;
                cp_async16(a_off0+fb*STAGE_BYTES,Ap+ko,abytes);
                cp_async16(a_off0+fb*STAGE_BYTES+16,Ap+ko+4,abytes);
                #pragma unroll
                for(int r=0;r<4;++r)
                    cp_async16(b_off0+fb*STAGE_BYTES+r*(4*136*4),
                               Bp+ko*N+(size_t)(r*4)*N,16);
            }
            cp_commit();

            const uint32_t* As=(const uint32_t*)(smem+s*STAGE_FLOATS);
            const uint32_t* Bs=As+A_FLOATS;

            #pragma unroll
            for(int ks=0;ks<2;++ks){
                const int kk=ks*8;
                uint32_t a[2][4], b[8][2];
                #pragma unroll
                for(int mf=0;mf<2;++mf){
                    const int mr=wm+mf*16+gid;
                    a[mf][0]=As[(mr   )*20+kk+tig];
                    a[mf][1]=As[(mr+8)*20+kk+tig];
                    a[mf][2]=As[(mr   )*20+kk+tig+4];
                    a[mf][3]=As[(mr+8)*20+kk+tig+4];
                }
                #pragma unroll
                for(int nf=0;nf<8;++nf){
                    const int nc=wn+nf*8+gid;
                    b[nf][0]=Bs[(kk+tig   )*136+nc];
                    b[nf][1]=Bs[(kk+tig+4)*136+nc];
                }
                #pragma unroll
                for(int mf=0;mf<2;++mf)
                    #pragma unroll
                    for(int nf=0;nf<8;++nf)
                        MMA_TF32(acc[mf][nf],a[mf],b[nf]);
            }
        }
    }

    // epilogue
    if(fuseSilu){
        // fragments nf<4: g (cols n0g+wnum*32+nf*8+tig*2), nf+4: u same cols
        #pragma unroll
        for(int mf=0;mf<2;++mf){
            #pragma unroll
            for(int half=0;half<2;++half){
                const int rloc=wm+mf*16+gid+half*8;
                if(m0+rloc<m_count){
                    const int grow=base+m0+rloc;
                    float* crow=Cuse+(size_t)grow*IDIM+n0g+wnum*32;
                    #pragma unroll
                    for(int nf=0;nf<4;++nf){
                        float g0=acc[mf][nf  ][half*2+0]*CORR;
                        float g1=acc[mf][nf  ][half*2+1]*CORR;
                        float u0=acc[mf][nf+4][half*2+0]*CORR;
                        float u1=acc[mf][nf+4][half*2+1]*CORR;
                        float2 v;
                        v.x=g0/(1.f+__expf(-g0))*u0;
                        v.y=g1/(1.f+__expf(-g1))*u1;
                        *(float2*)(crow+nf*8+tig*2)=v;
                    }
                }
            }
        }
    } else {
        #pragma unroll
        for(int mf=0;mf<2;++mf){
            #pragma unroll
            for(int half=0;half<2;++half){
                const int rloc=wm+mf*16+gid+half*8;
                if(m0+rloc<m_count){
                    const int grow=base+m0+rloc;
                    const float scl=(rscale?rscale[grow]:1.f)*CORR;
                    const int orow=omap?omap[grow]:grow;
                    float* crow=Cuse+(size_t)orow*N+n0+wn;
                    if(omap){
                        #pragma unroll
                        for(int nf=0;nf<8;++nf){
                            atomicAdd(crow+nf*8+tig*2,   acc[mf][nf][half*2+0]*scl);
                            atomicAdd(crow+nf*8+tig*2+1, acc[mf][nf][half*2+1]*scl);
                        }
                    } else {
                        #pragma unroll
                        for(int nf=0;nf<8;++nf){
                            float2 v;
                            v.x=acc[mf][nf][half*2+0]*scl;
                            v.y=acc[mf][nf][half*2+1]*scl;
                            *(float2*)(crow+nf*8+tig*2)=v;
                        }
                    }
                }
            }
        }
    }
}

// --------------------------- launch -----------------------------------------
extern "C" void kernel_launch(void* const* d_in,const int* in_sizes,int n_in,
                              void* d_out,int out_size)
{
    const float* hidden   =(const float*)d_in[0];
    const float* gate_w   =(const float*)d_in[1];
    const float* e_bias   =(const float*)d_in[2];
    const float* w_gate_up=(const float*)d_in[3];
    const float* w_down   =(const float*)d_in[4];
    const float* sh_gu    =(const float*)d_in[5];
    const float* sh_down  =(const float*)d_in[6];
    float* out            =(float*)d_out;

    void *p_act,*p_act_s,*p_counts,*p_offsets,*p_stok,*p_sws;
    cudaGetSymbolAddress(&p_act,g_act);
    cudaGetSymbolAddress(&p_act_s,g_act_s);
    cudaGetSymbolAddress(&p_counts,g_counts);
    cudaGetSymbolAddress(&p_offsets,g_offsets);
    cudaGetSymbolAddress(&p_stok,g_sorted_token);
    cudaGetSymbolAddress(&p_sws,g_sorted_ws);

    static bool attr_set=false;
    if(!attr_set){
        cudaFuncSetAttribute(gemm_tf32_kernel,
                             cudaFuncAttributeMaxDynamicSharedMemorySize,
                             GEMM_SMEM_BYTES);
        attr_set=true;
    }

    // 0-2: router + fused count/scan + place
    router_kernel<<<TTOK,32>>>(hidden,gate_w,e_bias);
    countscan_kernel<<<1,256>>>();
    place_kernel<<<EXP,256>>>();

    // 3 (ncu profiles this): MERGED gate_up GEMM with FUSED silu*mul epilogue
    // z<32 routed (writes g_act), z==32 shared (writes g_act_s).
    gemm_tf32_kernel<<<dim3(16,IDIM/64,EXP+1),128,GEMM_SMEM_BYTES>>>(
        hidden,w_gate_up,(float*)p_act, 0,2*IDIM,HDIM,
        (const int*)p_counts,(const int*)p_offsets,(const int*)p_stok,nullptr,
        (size_t)HDIM*2*IDIM,
        hidden,sh_gu,(float*)p_act_s,TTOK, nullptr, 1);

    // shared down-proj: writes out directly (initializes every element)
    gemm_tf32_kernel<<<dim3(16,HDIM/BN,1),128,GEMM_SMEM_BYTES>>>(
        (const float*)p_act_s,sh_down,out, TTOK,HDIM,IDIM,
        nullptr,nullptr,nullptr,nullptr,0,
        nullptr,nullptr,nullptr,0, nullptr, 0);

    // routed down-proj: atomically accumulates w*2.5*y into out[token]
    gemm_tf32_kernel<<<dim3(16,HDIM/BN,EXP),128,GEMM_SMEM_BYTES>>>(
        (const float*)p_act,w_down,out, 0,HDIM,IDIM,
        (const int*)p_counts,(const int*)p_offsets,nullptr,
        (const float*)p_sws,(size_t)IDIM*HDIM,
        nullptr,nullptr,nullptr,0, (const int*)p_stok, 0);
}

// round 16
// speedup vs baseline: 1.4532x; 1.1194x over previous
#include <cuda_runtime.h>
#include <cstdint>

constexpr int TTOK=1024, HDIM=2048, EXP=32, IDIM=1024, TOPK=6, NGRP=8, TOPKG=4;
constexpr int GSIZE=EXP/NGRP, PAIRS=TTOK*TOPK;
constexpr float RSCALE=2.5f, CORR=1.0007045f;

__device__ int   g_topk_id[PAIRS];
__device__ float g_topk_w[PAIRS];
__device__ int   g_counts[EXP];
__device__ int   g_offsets[EXP];
__device__ int   g_sorted_token[PAIRS];
__device__ float g_sorted_ws[PAIRS];              // topk_w * 2.5
__device__ float g_act  [(size_t)PAIRS*IDIM];     // 24MB (silu(g)*u, routed)
__device__ float g_act_s[(size_t)TTOK*IDIM];      // 4MB  (silu(g)*u, shared)

// ------------------------------ router -------------------------------------
// 256 threads/token: lane = expert, seg = h-segment (8 x 256). Selection
// logic on lane 0 of seg 0 is byte-identical to the validated version.
__global__ void router_kernel(const float* __restrict__ hidden,
                              const float* __restrict__ gate_w,
                              const float* __restrict__ e_bias)
{
    int t=blockIdx.x;
    int tid=threadIdx.x, lane=tid&31, seg=tid>>5;      // seg 0..7
    const float* x=hidden+(size_t)t*HDIM;

    float partial=0.f;
    const int h0=seg*(HDIM/8), h1=h0+(HDIM/8);
    #pragma unroll 8
    for(int h=h0;h<h1;++h) partial+=x[h]*gate_w[(size_t)h*EXP+lane];

    __shared__ float part[8][EXP];
    part[seg][lane]=partial;
    __syncthreads();

    __shared__ float sm_s[EXP], sm_sc[EXP];
    if(seg==0){
        float logit=0.f;
        #pragma unroll
        for(int s8=0;s8<8;++s8) logit+=part[s8][lane];
        float s=1.f/(1.f+expf(-logit));
        sm_s[lane]=s; sm_sc[lane]=s+e_bias[lane];
    }
    __syncthreads();

    if(tid==0){
        float gs[NGRP];
        #pragma unroll
        for(int g=0;g<NGRP;++g){
            float m1=-1e30f,m2=-1e30f;
            #pragma unroll
            for(int j=0;j<GSIZE;++j){
                float v=sm_sc[g*GSIZE+j];
                if(v>m1){m2=m1;m1=v;} else if(v>m2){m2=v;}
            }
            gs[g]=m1+m2;
        }
        bool gsel[NGRP];
        #pragma unroll
        for(int g=0;g<NGRP;++g) gsel[g]=false;
        for(int it=0;it<TOPKG;++it){
            int best=-1; float bv=-1e30f;
            for(int g=0;g<NGRP;++g) if(!gsel[g]&&gs[g]>bv){bv=gs[g];best=g;}
            gsel[best]=true;
        }
        bool taken[EXP];
        #pragma unroll
        for(int e=0;e<EXP;++e) taken[e]=false;
        int ids[TOPK]; float ws[TOPK]; float wsum=0.f;
        for(int it=0;it<TOPK;++it){
            int best=-1; float bv=-1e30f;
            for(int e=0;e<EXP;++e){
                if(!gsel[e>>2]||taken[e]) continue;
                if(sm_sc[e]>bv){bv=sm_sc[e];best=e;}
            }
            taken[best]=true; ids[it]=best; ws[it]=sm_s[best]; wsum+=ws[it];
        }
        float inv=1.f/wsum;
        #pragma unroll
        for(int k=0;k<TOPK;++k){
            g_topk_id[t*TOPK+k]=ids[k];
            g_topk_w [t*TOPK+k]=ws[k]*inv;
        }
    }
}

// ---------------- count+scan fused (single block) ---------------------------
__global__ void countscan_kernel()
{
    __shared__ int hist[EXP];
    int tid=threadIdx.x;
    if(tid<EXP) hist[tid]=0;
    __syncthreads();
    for(int p=tid;p<PAIRS;p+=blockDim.x) atomicAdd(&hist[g_topk_id[p]],1);
    __syncthreads();
    if(tid==0){
        int acc=0;
        for(int e=0;e<EXP;++e){ g_counts[e]=hist[e]; g_offsets[e]=acc; acc+=hist[e]; }
    }
}

__global__ void place_kernel()
{
    int e=blockIdx.x, tid=threadIdx.x;
    constexpr int CH=PAIRS/256;
    int p0=tid*CH, c=0;
    for(int i=0;i<CH;++i) c+=(g_topk_id[p0+i]==e);
    __shared__ int sc[256];
    sc[tid]=c; __syncthreads();
    for(int d=1;d<256;d<<=1){
        int v=(tid>=d)?sc[tid-d]:0; __syncthreads();
        sc[tid]+=v; __syncthreads();
    }
    int pos=g_offsets[e]+sc[tid]-c;
    for(int i=0;i<CH;++i){
        int p=p0+i;
        if(g_topk_id[p]==e){
            g_sorted_token[pos]=p/TOPK;
            g_sorted_ws[pos]=g_topk_w[p]*RSCALE;
            ++pos;
        }
    }
}

// --------------------------- tf32 GEMM core ---------------------------------
__device__ __forceinline__ void cp_async16(uint32_t dst,const void* src,int bytes)
{ asm volatile("cp.async.cg.shared.global [%0], [%1], 16, %2;\n"::"r"(dst),"l"(src),"r"(bytes)); }
__device__ __forceinline__ void cp_commit(){ asm volatile("cp.async.commit_group;\n"); }
template<int N> __device__ __forceinline__ void cp_wait()
{ asm volatile("cp.async.wait_group %0;\n"::"n"(N)); }

#define MMA_TF32(d, a, b)                                                  \
    asm volatile(                                                          \
        "mma.sync.aligned.m16n8k8.row.col.f32.tf32.tf32.f32 "              \
        "{%0,%1,%2,%3}, {%4,%5,%6,%7}, {%8,%9}, {%0,%1,%2,%3};\n"          \
        : "+f"(d[0]), "+f"(d[1]), "+f"(d[2]), "+f"(d[3])                   \
        : "r"(a[0]), "r"(a[1]), "r"(a[2]), "r"(a[3]), "r"(b[0]), "r"(b[1]))

// BM=64, BN=128, BK=16, 128 threads, 4 warps (2m x 2n), warp tile 32x64.
// 4-stage cp.async pipeline (best-measured core: tensor 52%).
// fuseSilu: fragments nf<4 hold g, nf>=4 hold u for the same output columns;
// epilogue writes silu(g*CORR)*(u*CORR) (stride IDIM).
// A2 branch: blockIdx.z == gridDim.z-1 -> shared expert.
// outmap: epilogue atomically accumulates into C[outmap[row]].
// sharedAtomic: shared-expert branch also uses atomicAdd (merged down-proj).
constexpr int STAGES=4;
constexpr int BN=128;
constexpr int A_FLOATS=64*20;
constexpr int B_FLOATS=16*136;
constexpr int STAGE_FLOATS=A_FLOATS+B_FLOATS;          // 3456
constexpr int GEMM_SMEM_BYTES=STAGES*STAGE_FLOATS*4;   // 55296

__global__ __launch_bounds__(128,4)
void gemm_tf32_kernel(const float* __restrict__ A,
                      const float* __restrict__ Bb,
                      float* __restrict__ C,
                      int M,int N,int K,
                      const int* __restrict__ counts,
                      const int* __restrict__ offsets,
                      const int* __restrict__ rowmap,
                      const float* __restrict__ rowscale,
                      size_t strideB,
                      const float* __restrict__ A2,
                      const float* __restrict__ B2,
                      float* __restrict__ C2,
                      int M2,
                      const int* __restrict__ outmap,
                      int fuseSilu,
                      int sharedAtomic)
{
    extern __shared__ float smem[];

    const int e=blockIdx.z;
    const bool isShared=(A2!=nullptr)&&(e==(int)gridDim.z-1);

    const float* Ause; const float* Buse; float* Cuse;
    int m_count, base;
    const int* rmap; const float* rscale; const int* omap;
    bool useAtomic;
    if(isShared){
        Ause=A2; Buse=B2; Cuse=C2; m_count=M2; base=0;
        rmap=nullptr; rscale=nullptr; omap=nullptr;
        useAtomic=(sharedAtomic!=0);
    } else {
        Ause=A; Buse=Bb+(size_t)e*strideB; Cuse=C;
        m_count=counts?counts[e]:M; base=offsets?offsets[e]:0;
        rmap=rowmap; rscale=rowscale; omap=outmap;
        useAtomic=(omap!=nullptr);
    }

    const int m0=blockIdx.x*64;
    if(m0>=m_count) return;
    const int n0 =blockIdx.y*BN;     // plain GEMM: 128 output cols
    const int n0g=blockIdx.y*64;     // fused: 64 activation cols

    const int tid=threadIdx.x;

    // A loader: thread owns row ar, two k-quads
    const int ar=tid>>1;
    const int aq=(tid&1)*2;
    const bool avalid=(m0+ar)<m_count;
    const int grow_a=base+m0+ar;
    const int arow=avalid?(rmap?rmap[grow_a]:grow_a):0;
    const float* Ap=Ause+(size_t)arow*K+aq*4;
    const int abytes=avalid?16:0;

    // B loader: k-rows bkr+{0,4,8,12}, n-quad bnq.
    const int bkr=tid>>5;
    const int bnq=tid&31;
    const int c0=bnq*4;
    int bcol;
    if(fuseSilu){
        const int w=c0>>6, cw=c0&63;
        bcol=(cw<32)?(n0g+w*32+cw):(IDIM+n0g+w*32+(cw-32));
    } else {
        bcol=n0+c0;
    }
    const float* Bp=Buse+(size_t)bkr*N+bcol;

    const int wid=tid>>5, lane=tid&31;
    const int wm=(wid>>1)*32, wn=(wid&1)*64;
    const int wnum=wid&1;
    const int gid=lane>>2, tig=lane&3;

    float acc[2][8][4];
    #pragma unroll
    for(int i=0;i<2;++i)
        #pragma unroll
        for(int j=0;j<8;++j)
            #pragma unroll
            for(int k=0;k<4;++k) acc[i][j][k]=0.f;

    const int nk=K/16;   // 64 or 128; divisible by 4

    const uint32_t smem_base=(uint32_t)__cvta_generic_to_shared(smem);
    const uint32_t a_off0=smem_base+(ar*20+aq*4)*4;
    const uint32_t b_off0=smem_base+(A_FLOATS+bkr*136+bnq*4)*4;
    constexpr uint32_t STAGE_BYTES=STAGE_FLOATS*4;

    #pragma unroll
    for(int s=0;s<STAGES-1;++s){
        const size_t ko=(size_t)s*16;
        cp_async16(a_off0+s*STAGE_BYTES,Ap+ko,abytes);
        cp_async16(a_off0+s*STAGE_BYTES+16,Ap+ko+4,abytes);
        #pragma unroll
        for(int r=0;r<4;++r)
            cp_async16(b_off0+s*STAGE_BYTES+r*(4*136*4),
                       Bp+ko*N+(size_t)(r*4)*N,16);
        cp_commit();
    }

    for(int kb=0;kb<nk;kb+=STAGES){
        #pragma unroll
        for(int s=0;s<STAGES;++s){
            const int kt=kb+s;
            cp_wait<STAGES-2>();
            __syncthreads();

            const int kf=kt+STAGES-1;
            if(kf<nk){
                const int fb=(s+STAGES-1)%STAGES;
                const size_t ko=(size_t)kf*16;
                cp_async16(a_off0+fb*STAGE_BYTES,Ap+ko,abytes);
                cp_async16(a_off0+fb*STAGE_BYTES+16,Ap+ko+4,abytes);
                #pragma unroll
                for(int r=0;r<4;++r)
                    cp_async16(b_off0+fb*STAGE_BYTES+r*(4*136*4),
                               Bp+ko*N+(size_t)(r*4)*N,16);
            }
            cp_commit();

            const uint32_t* As=(const uint32_t*)(smem+s*STAGE_FLOATS);
            const uint32_t* Bs=As+A_FLOATS;

            #pragma unroll
            for(int ks=0;ks<2;++ks){
                const int kk=ks*8;
                uint32_t a[2][4], b[8][2];
                #pragma unroll
                for(int mf=0;mf<2;++mf){
                    const int mr=wm+mf*16+gid;
                    a[mf][0]=As[(mr   )*20+kk+tig];
                    a[mf][1]=As[(mr+8)*20+kk+tig];
                    a[mf][2]=As[(mr   )*20+kk+tig+4];
                    a[mf][3]=As[(mr+8)*20+kk+tig+4];
                }
                #pragma unroll
                for(int nf=0;nf<8;++nf){
                    const int nc=wn+nf*8+gid;
                    b[nf][0]=Bs[(kk+tig   )*136+nc];
                    b[nf][1]=Bs[(kk+tig+4)*136+nc];
                }
                #pragma unroll
                for(int mf=0;mf<2;++mf)
                    #pragma unroll
                    for(int nf=0;nf<8;++nf)
                        MMA_TF32(acc[mf][nf],a[mf],b[nf]);
            }
        }
    }

    // epilogue
    if(fuseSilu){
        #pragma unroll
        for(int mf=0;mf<2;++mf){
            #pragma unroll
            for(int half=0;half<2;++half){
                const int rloc=wm+mf*16+gid+half*8;
                if(m0+rloc<m_count){
                    const int grow=base+m0+rloc;
                    float* crow=Cuse+(size_t)grow*IDIM+n0g+wnum*32;
                    #pragma unroll
                    for(int nf=0;nf<4;++nf){
                        float g0=acc[mf][nf  ][half*2+0]*CORR;
                        float g1=acc[mf][nf  ][half*2+1]*CORR;
                        float u0=acc[mf][nf+4][half*2+0]*CORR;
                        float u1=acc[mf][nf+4][half*2+1]*CORR;
                        float2 v;
                        v.x=g0/(1.f+__expf(-g0))*u0;
                        v.y=g1/(1.f+__expf(-g1))*u1;
                        *(float2*)(crow+nf*8+tig*2)=v;
                    }
                }
            }
        }
    } else {
        #pragma unroll
        for(int mf=0;mf<2;++mf){
            #pragma unroll
            for(int half=0;half<2;++half){
                const int rloc=wm+mf*16+gid+half*8;
                if(m0+rloc<m_count){
                    const int grow=base+m0+rloc;
                    const float scl=(rscale?rscale[grow]:1.f)*CORR;
                    const int orow=omap?omap[grow]:grow;
                    float* crow=Cuse+(size_t)orow*N+n0+wn;
                    if(useAtomic){
                        #pragma unroll
                        for(int nf=0;nf<8;++nf){
                            atomicAdd(crow+nf*8+tig*2,   acc[mf][nf][half*2+0]*scl);
                            atomicAdd(crow+nf*8+tig*2+1, acc[mf][nf][half*2+1]*scl);
                        }
                    } else {
                        #pragma unroll
                        for(int nf=0;nf<8;++nf){
                            float2 v;
                            v.x=acc[mf][nf][half*2+0]*scl;
                            v.y=acc[mf][nf][half*2+1]*scl;
                            *(float2*)(crow+nf*8+tig*2)=v;
                        }
                    }
                }
            }
        }
    }
}

// --------------------------- launch -----------------------------------------
extern "C" void kernel_launch(void* const* d_in,const int* in_sizes,int n_in,
                              void* d_out,int out_size)
{
    const float* hidden   =(const float*)d_in[0];
    const float* gate_w   =(const float*)d_in[1];
    const float* e_bias   =(const float*)d_in[2];
    const float* w_gate_up=(const float*)d_in[3];
    const float* w_down   =(const float*)d_in[4];
    const float* sh_gu    =(const float*)d_in[5];
    const float* sh_down  =(const float*)d_in[6];
    float* out            =(float*)d_out;

    void *p_act,*p_act_s,*p_counts,*p_offsets,*p_stok,*p_sws;
    cudaGetSymbolAddress(&p_act,g_act);
    cudaGetSymbolAddress(&p_act_s,g_act_s);
    cudaGetSymbolAddress(&p_counts,g_counts);
    cudaGetSymbolAddress(&p_offsets,g_offsets);
    cudaGetSymbolAddress(&p_stok,g_sorted_token);
    cudaGetSymbolAddress(&p_sws,g_sorted_ws);

    static bool attr_set=false;
    if(!attr_set){
        cudaFuncSetAttribute(gemm_tf32_kernel,
                             cudaFuncAttributeMaxDynamicSharedMemorySize,
                             GEMM_SMEM_BYTES);
        attr_set=true;
    }

    // 0-2: router + fused count/scan + place
    router_kernel<<<TTOK,256>>>(hidden,gate_w,e_bias);
    countscan_kernel<<<1,256>>>();
    place_kernel<<<EXP,256>>>();

    // 3 (ncu profiles this): MERGED gate_up GEMM with FUSED silu*mul epilogue
    // z<32 routed (writes g_act), z==32 shared (writes g_act_s).
    gemm_tf32_kernel<<<dim3(16,IDIM/64,EXP+1),128,GEMM_SMEM_BYTES>>>(
        hidden,w_gate_up,(float*)p_act, 0,2*IDIM,HDIM,
        (const int*)p_counts,(const int*)p_offsets,(const int*)p_stok,nullptr,
        (size_t)HDIM*2*IDIM,
        hidden,sh_gu,(float*)p_act_s,TTOK, nullptr, 1, 0);

    // zero out (graph-legal memset node); both down-proj paths accumulate
    cudaMemsetAsync(out,0,(size_t)TTOK*HDIM*sizeof(float));

    // MERGED down-proj: z<32 routed (atomic w*2.5*y into out[token]),
    // z==32 shared (atomic silu-act @ sh_down into out[token]).
    gemm_tf32_kernel<<<dim3(16,HDIM/BN,EXP+1),128,GEMM_SMEM_BYTES>>>(
        (const float*)p_act,w_down,out, 0,HDIM,IDIM,
        (const int*)p_counts,(const int*)p_offsets,nullptr,
        (const float*)p_sws,(size_t)IDIM*HDIM,
        (const float*)p_act_s,sh_down,out,TTOK, (const int*)p_stok, 0, 1);
}

// round 17
// speedup vs baseline: 1.5380x; 1.0583x over previous
#include <cuda_runtime.h>
#include <cstdint>

constexpr int TTOK=1024, HDIM=2048, EXP=32, IDIM=1024, TOPK=6, NGRP=8, TOPKG=4;
constexpr int GSIZE=EXP/NGRP, PAIRS=TTOK*TOPK;
constexpr float RSCALE=2.5f, CORR=1.0007045f;

__device__ int   g_topk_id[PAIRS];
__device__ float g_topk_w[PAIRS];
__device__ int   g_counts[EXP];
__device__ int   g_offsets[EXP];
__device__ int   g_sorted_token[PAIRS];
__device__ float g_sorted_ws[PAIRS];              // topk_w * 2.5
__device__ float g_act  [(size_t)PAIRS*IDIM];     // 24MB (silu(g)*u, routed)
__device__ float g_act_s[(size_t)TTOK*IDIM];      // 4MB  (silu(g)*u, shared)

// ------------------------------ router -------------------------------------
__global__ void router_kernel(const float* __restrict__ hidden,
                              const float* __restrict__ gate_w,
                              const float* __restrict__ e_bias)
{
    int t=blockIdx.x;
    int tid=threadIdx.x, lane=tid&31, seg=tid>>5;      // seg 0..7
    const float* x=hidden+(size_t)t*HDIM;

    float partial=0.f;
    const int h0=seg*(HDIM/8), h1=h0+(HDIM/8);
    #pragma unroll 8
    for(int h=h0;h<h1;++h) partial+=x[h]*gate_w[(size_t)h*EXP+lane];

    __shared__ float part[8][EXP];
    part[seg][lane]=partial;
    __syncthreads();

    __shared__ float sm_s[EXP], sm_sc[EXP];
    if(seg==0){
        float logit=0.f;
        #pragma unroll
        for(int s8=0;s8<8;++s8) logit+=part[s8][lane];
        float s=1.f/(1.f+expf(-logit));
        sm_s[lane]=s; sm_sc[lane]=s+e_bias[lane];
    }
    __syncthreads();

    if(tid==0){
        float gs[NGRP];
        #pragma unroll
        for(int g=0;g<NGRP;++g){
            float m1=-1e30f,m2=-1e30f;
            #pragma unroll
            for(int j=0;j<GSIZE;++j){
                float v=sm_sc[g*GSIZE+j];
                if(v>m1){m2=m1;m1=v;} else if(v>m2){m2=v;}
            }
            gs[g]=m1+m2;
        }
        bool gsel[NGRP];
        #pragma unroll
        for(int g=0;g<NGRP;++g) gsel[g]=false;
        for(int it=0;it<TOPKG;++it){
            int best=-1; float bv=-1e30f;
            for(int g=0;g<NGRP;++g) if(!gsel[g]&&gs[g]>bv){bv=gs[g];best=g;}
            gsel[best]=true;
        }
        bool taken[EXP];
        #pragma unroll
        for(int e=0;e<EXP;++e) taken[e]=false;
        int ids[TOPK]; float ws[TOPK]; float wsum=0.f;
        for(int it=0;it<TOPK;++it){
            int best=-1; float bv=-1e30f;
            for(int e=0;e<EXP;++e){
                if(!gsel[e>>2]||taken[e]) continue;
                if(sm_sc[e]>bv){bv=sm_sc[e];best=e;}
            }
            taken[best]=true; ids[it]=best; ws[it]=sm_s[best]; wsum+=ws[it];
        }
        float inv=1.f/wsum;
        #pragma unroll
        for(int k=0;k<TOPK;++k){
            g_topk_id[t*TOPK+k]=ids[k];
            g_topk_w [t*TOPK+k]=ws[k]*inv;
        }
    }
}

// ---------------- count+scan fused (single block) ---------------------------
__global__ void countscan_kernel()
{
    __shared__ int hist[EXP];
    int tid=threadIdx.x;
    if(tid<EXP) hist[tid]=0;
    __syncthreads();
    for(int p=tid;p<PAIRS;p+=blockDim.x) atomicAdd(&hist[g_topk_id[p]],1);
    __syncthreads();
    if(tid==0){
        int acc=0;
        for(int e=0;e<EXP;++e){ g_counts[e]=hist[e]; g_offsets[e]=acc; acc+=hist[e]; }
    }
}

__global__ void place_kernel()
{
    int e=blockIdx.x, tid=threadIdx.x;
    constexpr int CH=PAIRS/256;
    int p0=tid*CH, c=0;
    for(int i=0;i<CH;++i) c+=(g_topk_id[p0+i]==e);
    __shared__ int sc[256];
    sc[tid]=c; __syncthreads();
    for(int d=1;d<256;d<<=1){
        int v=(tid>=d)?sc[tid-d]:0; __syncthreads();
        sc[tid]+=v; __syncthreads();
    }
    int pos=g_offsets[e]+sc[tid]-c;
    for(int i=0;i<CH;++i){
        int p=p0+i;
        if(g_topk_id[p]==e){
            g_sorted_token[pos]=p/TOPK;
            g_sorted_ws[pos]=g_topk_w[p]*RSCALE;
            ++pos;
        }
    }
}

// --------------------------- tf32 GEMM core ---------------------------------
__device__ __forceinline__ void cp_async16(uint32_t dst,const void* src,int bytes)
{ asm volatile("cp.async.cg.shared.global [%0], [%1], 16, %2;\n"::"r"(dst),"l"(src),"r"(bytes)); }
__device__ __forceinline__ void cp_commit(){ asm volatile("cp.async.commit_group;\n"); }
template<int N> __device__ __forceinline__ void cp_wait()
{ asm volatile("cp.async.wait_group %0;\n"::"n"(N)); }

#define MMA_TF32(d, a, b)                                                  \
    asm volatile(                                                          \
        "mma.sync.aligned.m16n8k8.row.col.f32.tf32.tf32.f32 "              \
        "{%0,%1,%2,%3}, {%4,%5,%6,%7}, {%8,%9}, {%0,%1,%2,%3};\n"          \
        : "+f"(d[0]), "+f"(d[1]), "+f"(d[2]), "+f"(d[3])                   \
        : "r"(a[0]), "r"(a[1]), "r"(a[2]), "r"(a[3]), "r"(b[0]), "r"(b[1]))

#define LDSM_X4(r, addr)                                                   \
    asm volatile("ldmatrix.sync.aligned.m8n8.x4.shared.b16 "               \
                 "{%0,%1,%2,%3}, [%4];"                                    \
                 : "=r"((r)[0]), "=r"((r)[1]), "=r"((r)[2]), "=r"((r)[3])  \
                 : "r"(addr))

// BM=64, BN=128, BK=16, 128 threads, 4 warps (2m x 2n), warp tile 32x64.
// 4-stage cp.async pipeline. A fragments loaded via ldmatrix.x4 (one LDSM
// per m16k8 fragment; As stride 20 floats keeps rows 16B-aligned and the
// 8 row-addresses per matrix bank-disjoint). B fragments remain scalar LDS.
// fuseSilu: fragments nf<4 hold g, nf>=4 hold u for the same output columns;
// epilogue writes silu(g*CORR)*(u*CORR) (stride IDIM).
// A2 branch: blockIdx.z == gridDim.z-1 -> shared expert.
// outmap: epilogue atomically accumulates into C[outmap[row]].
constexpr int STAGES=4;
constexpr int BN=128;
constexpr int A_FLOATS=64*20;
constexpr int B_FLOATS=16*136;
constexpr int STAGE_FLOATS=A_FLOATS+B_FLOATS;          // 3456
constexpr int GEMM_SMEM_BYTES=STAGES*STAGE_FLOATS*4;   // 55296

__global__ __launch_bounds__(128,4)
void gemm_tf32_kernel(const float* __restrict__ A,
                      const float* __restrict__ Bb,
                      float* __restrict__ C,
                      int M,int N,int K,
                      const int* __restrict__ counts,
                      const int* __restrict__ offsets,
                      const int* __restrict__ rowmap,
                      const float* __restrict__ rowscale,
                      size_t strideB,
                      const float* __restrict__ A2,
                      const float* __restrict__ B2,
                      float* __restrict__ C2,
                      int M2,
                      const int* __restrict__ outmap,
                      int fuseSilu,
                      int sharedAtomic)
{
    extern __shared__ float smem[];

    const int e=blockIdx.z;
    const bool isShared=(A2!=nullptr)&&(e==(int)gridDim.z-1);

    const float* Ause; const float* Buse; float* Cuse;
    int m_count, base;
    const int* rmap; const float* rscale; const int* omap;
    bool useAtomic;
    if(isShared){
        Ause=A2; Buse=B2; Cuse=C2; m_count=M2; base=0;
        rmap=nullptr; rscale=nullptr; omap=nullptr;
        useAtomic=(sharedAtomic!=0);
    } else {
        Ause=A; Buse=Bb+(size_t)e*strideB; Cuse=C;
        m_count=counts?counts[e]:M; base=offsets?offsets[e]:0;
        rmap=rowmap; rscale=rowscale; omap=outmap;
        useAtomic=(omap!=nullptr);
    }

    const int m0=blockIdx.x*64;
    if(m0>=m_count) return;
    const int n0 =blockIdx.y*BN;     // plain GEMM: 128 output cols
    const int n0g=blockIdx.y*64;     // fused: 64 activation cols

    const int tid=threadIdx.x;

    // A loader: thread owns row ar, two k-quads
    const int ar=tid>>1;
    const int aq=(tid&1)*2;
    const bool avalid=(m0+ar)<m_count;
    const int grow_a=base+m0+ar;
    const int arow=avalid?(rmap?rmap[grow_a]:grow_a):0;
    const float* Ap=Ause+(size_t)arow*K+aq*4;
    const int abytes=avalid?16:0;

    // B loader: k-rows bkr+{0,4,8,12}, n-quad bnq.
    const int bkr=tid>>5;
    const int bnq=tid&31;
    const int c0=bnq*4;
    int bcol;
    if(fuseSilu){
        const int w=c0>>6, cw=c0&63;
        bcol=(cw<32)?(n0g+w*32+cw):(IDIM+n0g+w*32+(cw-32));
    } else {
        bcol=n0+c0;
    }
    const float* Bp=Buse+(size_t)bkr*N+bcol;

    const int wid=tid>>5, lane=tid&31;
    const int wm=(wid>>1)*32, wn=(wid&1)*64;
    const int wnum=wid&1;
    const int gid=lane>>2, tig=lane&3;

    // ldmatrix A addressing: matrix i = lanes 8i..8i+7
    const int a_r=(lane&7)+((lane>>3)&1)*8;   // row within 16-row fragment
    const int a_c=(lane>>4)*4;                // k-col 0 or 4

    float acc[2][8][4];
    #pragma unroll
    for(int i=0;i<2;++i)
        #pragma unroll
        for(int j=0;j<8;++j)
            #pragma unroll
            for(int k=0;k<4;++k) acc[i][j][k]=0.f;

    const int nk=K/16;   // 64 or 128; divisible by 4

    const uint32_t smem_base=(uint32_t)__cvta_generic_to_shared(smem);
    const uint32_t a_off0=smem_base+(ar*20+aq*4)*4;
    const uint32_t b_off0=smem_base+(A_FLOATS+bkr*136+bnq*4)*4;
    // per-thread ldmatrix base (stage 0, mf 0, kk 0)
    const uint32_t lm_base=smem_base+((wm+a_r)*20+a_c)*4;
    constexpr uint32_t STAGE_BYTES=STAGE_FLOATS*4;

    #pragma unroll
    for(int s=0;s<STAGES-1;++s){
        const size_t ko=(size_t)s*16;
        cp_async16(a_off0+s*STAGE_BYTES,Ap+ko,abytes);
        cp_async16(a_off0+s*STAGE_BYTES+16,Ap+ko+4,abytes);
        #pragma unroll
        for(int r=0;r<4;++r)
            cp_async16(b_off0+s*STAGE_BYTES+r*(4*136*4),
                       Bp+ko*N+(size_t)(r*4)*N,16);
        cp_commit();
    }

    for(int kb=0;kb<nk;kb+=STAGES){
        #pragma unroll
        for(int s=0;s<STAGES;++s){
            const int kt=kb+s;
            cp_wait<STAGES-2>();
            __syncthreads();

            const int kf=kt+STAGES-1;
            if(kf<nk){
                const int fb=(s+STAGES-1)%STAGES;
                const size_t ko=(size_t)kf*16;
                cp_async16(a_off0+fb*STAGE_BYTES,Ap+ko,abytes);
                cp_async16(a_off0+fb*STAGE_BYTES+16,Ap+ko+4,abytes);
                #pragma unroll
                for(int r=0;r<4;++r)
                    cp_async16(b_off0+fb*STAGE_BYTES+r*(4*136*4),
                               Bp+ko*N+(size_t)(r*4)*N,16);
            }
            cp_commit();

            const uint32_t* Bs=(const uint32_t*)(smem+s*STAGE_FLOATS)+A_FLOATS;
            const uint32_t lm_s=lm_base+s*STAGE_BYTES;

            #pragma unroll
            for(int ks=0;ks<2;++ks){
                const int kk=ks*8;
                uint32_t a[2][4], b[8][2];
                #pragma unroll
                for(int mf=0;mf<2;++mf)
                    LDSM_X4(a[mf], lm_s+(mf*16*20+kk)*4);
                #pragma unroll
                for(int nf=0;nf<8;++nf){
                    const int nc=wn+nf*8+gid;
                    b[nf][0]=Bs[(kk+tig   )*136+nc];
                    b[nf][1]=Bs[(kk+tig+4)*136+nc];
                }
                #pragma unroll
                for(int mf=0;mf<2;++mf)
                    #pragma unroll
                    for(int nf=0;nf<8;++nf)
                        MMA_TF32(acc[mf][nf],a[mf],b[nf]);
            }
        }
    }

    // epilogue
    if(fuseSilu){
        #pragma unroll
        for(int mf=0;mf<2;++mf){
            #pragma unroll
            for(int half=0;half<2;++half){
                const int rloc=wm+mf*16+gid+half*8;
                if(m0+rloc<m_count){
                    const int grow=base+m0+rloc;
                    float* crow=Cuse+(size_t)grow*IDIM+n0g+wnum*32;
                    #pragma unroll
                    for(int nf=0;nf<4;++nf){
                        float g0=acc[mf][nf  ][half*2+0]*CORR;
                        float g1=acc[mf][nf  ][half*2+1]*CORR;
                        float u0=acc[mf][nf+4][half*2+0]*CORR;
                        float u1=acc[mf][nf+4][half*2+1]*CORR;
                        float2 v;
                        v.x=g0/(1.f+__expf(-g0))*u0;
                        v.y=g1/(1.f+__expf(-g1))*u1;
                        *(float2*)(crow+nf*8+tig*2)=v;
                    }
                }
            }
        }
    } else {
        #pragma unroll
        for(int mf=0;mf<2;++mf){
            #pragma unroll
            for(int half=0;half<2;++half){
                const int rloc=wm+mf*16+gid+half*8;
                if(m0+rloc<m_count){
                    const int grow=base+m0+rloc;
                    const float scl=(rscale?rscale[grow]:1.f)*CORR;
                    const int orow=omap?omap[grow]:grow;
                    float* crow=Cuse+(size_t)orow*N+n0+wn;
                    if(useAtomic){
                        #pragma unroll
                        for(int nf=0;nf<8;++nf){
                            atomicAdd(crow+nf*8+tig*2,   acc[mf][nf][half*2+0]*scl);
                            atomicAdd(crow+nf*8+tig*2+1, acc[mf][nf][half*2+1]*scl);
                        }
                    } else {
                        #pragma unroll
                        for(int nf=0;nf<8;++nf){
                            float2 v;
                            v.x=acc[mf][nf][half*2+0]*scl;
                            v.y=acc[mf][nf][half*2+1]*scl;
                            *(float2*)(crow+nf*8+tig*2)=v;
                        }
                    }
                }
            }
        }
    }
}

// --------------------------- launch -----------------------------------------
extern "C" void kernel_launch(void* const* d_in,const int* in_sizes,int n_in,
                              void* d_out,int out_size)
{
    const float* hidden   =(const float*)d_in[0];
    const float* gate_w   =(const float*)d_in[1];
    const float* e_bias   =(const float*)d_in[2];
    const float* w_gate_up=(const float*)d_in[3];
    const float* w_down   =(const float*)d_in[4];
    const float* sh_gu    =(const float*)d_in[5];
    const float* sh_down  =(const float*)d_in[6];
    float* out            =(float*)d_out;

    void *p_act,*p_act_s,*p_counts,*p_offsets,*p_stok,*p_sws;
    cudaGetSymbolAddress(&p_act,g_act);
    cudaGetSymbolAddress(&p_act_s,g_act_s);
    cudaGetSymbolAddress(&p_counts,g_counts);
    cudaGetSymbolAddress(&p_offsets,g_offsets);
    cudaGetSymbolAddress(&p_stok,g_sorted_token);
    cudaGetSymbolAddress(&p_sws,g_sorted_ws);

    static bool attr_set=false;
    if(!attr_set){
        cudaFuncSetAttribute(gemm_tf32_kernel,
                             cudaFuncAttributeMaxDynamicSharedMemorySize,
                             GEMM_SMEM_BYTES);
        attr_set=true;
    }

    // 0-2: router + fused count/scan + place
    router_kernel<<<TTOK,256>>>(hidden,gate_w,e_bias);
    countscan_kernel<<<1,256>>>();
    place_kernel<<<EXP,256>>>();

    // 3 (ncu profiles this): MERGED gate_up GEMM with FUSED silu*mul epilogue
    // z<32 routed (writes g_act), z==32 shared (writes g_act_s).
    gemm_tf32_kernel<<<dim3(16,IDIM/64,EXP+1),128,GEMM_SMEM_BYTES>>>(
        hidden,w_gate_up,(float*)p_act, 0,2*IDIM,HDIM,
        (const int*)p_counts,(const int*)p_offsets,(const int*)p_stok,nullptr,
        (size_t)HDIM*2*IDIM,
        hidden,sh_gu,(float*)p_act_s,TTOK, nullptr, 1, 0);

    // zero out (graph-legal memset node); both down-proj paths accumulate
    cudaMemsetAsync(out,0,(size_t)TTOK*HDIM*sizeof(float));

    // MERGED down-proj: z<32 routed (atomic w*2.5*y into out[token]),
    // z==32 shared (atomic silu-act @ sh_down into out[token]).
    gemm_tf32_kernel<<<dim3(16,HDIM/BN,EXP+1),128,GEMM_SMEM_BYTES>>>(
        (const float*)p_act,w_down,out, 0,HDIM,IDIM,
        (const int*)p_counts,(const int*)p_offsets,nullptr,
        (const float*)p_sws,(size_t)IDIM*HDIM,
        (const float*)p_act_s,sh_down,out,TTOK, (const int*)p_stok, 0, 1);
}